// round 3
// baseline (speedup 1.0000x reference)
#include <cuda_runtime.h>
#include <math.h>

// ---------------- scratch (device globals; no runtime allocation) -------------
__device__ float g_h[(size_t)50000 * 512];   // per-layer projected features
__device__ float g_as[50000 * 8];            // per-(node,head) source attention coef
__device__ float g_ad[50000 * 8];            // per-(node,head) dest attention coef
__device__ float g_f1[50000 * 64];           // layer outputs ping
__device__ float g_f2[50000 * 64];           // layer outputs pong
__device__ int   g_deg[50000];
__device__ int   g_rowptr[50001];
__device__ int   g_wp[50000];
__device__ int   g_col[450000];              // CSR (by dst) of src ids, incl self loops
__device__ int   g_is32;                     // edge_index dtype flag: 1 = int32, 0 = int64

// buffer selectors: 0 = g_h, 1 = g_f1, 2 = g_f2
__device__ __forceinline__ float* selbuf(int s) {
    if (s == 0) return g_h;
    if (s == 1) return g_f1;
    return g_f2;
}

__device__ __forceinline__ int edge_at(const void* ei, long long idx, int is32) {
    return is32 ? ((const int*)ei)[idx] : (int)((const long long*)ei)[idx];
}

// ---------------- dtype detection: probe first 64 entries as int64 ------------
__global__ void k_detect(const void* __restrict__ ei, int n) {
    if (threadIdx.x != 0 || blockIdx.x != 0) return;
    const long long* p = (const long long*)ei;
    int bad = 0;
    for (int i = 0; i < 64; i++) {
        long long v = p[i];
        if (v < 0 || v >= (long long)n) bad = 1;
    }
    g_is32 = bad;
}

// ---------------- CSR build -------------
__global__ void k_initdeg(int n) {
    int i = blockIdx.x * blockDim.x + threadIdx.x;
    if (i < n) g_deg[i] = 1;  // self loop
}

__global__ void k_hist(const void* __restrict__ ei, int E, int n) {
    int i = blockIdx.x * blockDim.x + threadIdx.x;
    if (i >= E) return;
    int is32 = g_is32;
    int v = edge_at(ei, (long long)E + i, is32);
    if ((unsigned)v < (unsigned)n) atomicAdd(&g_deg[v], 1);
}

// single-block exclusive scan of g_deg -> g_rowptr, g_wp
__global__ void k_scan(int n) {
    __shared__ int sh[32];
    __shared__ int carry;
    int t = threadIdx.x;  // 1024 threads
    if (t == 0) carry = 0;
    __syncthreads();
    for (int base = 0; base < n; base += 1024) {
        int idx = base + t;
        int v = (idx < n) ? g_deg[idx] : 0;
        int x = v;
        #pragma unroll
        for (int o = 1; o < 32; o <<= 1) {
            int y = __shfl_up_sync(0xffffffffu, x, o);
            if ((t & 31) >= o) x += y;
        }
        if ((t & 31) == 31) sh[t >> 5] = x;
        __syncthreads();
        if (t < 32) {
            int y = sh[t];
            #pragma unroll
            for (int o = 1; o < 32; o <<= 1) {
                int z = __shfl_up_sync(0xffffffffu, y, o);
                if (t >= o) y += z;
            }
            sh[t] = y;
        }
        __syncthreads();
        int off = (t >= 32) ? sh[(t >> 5) - 1] : 0;
        int excl = x - v + off;
        int c = carry;
        if (idx < n) { g_rowptr[idx] = c + excl; g_wp[idx] = c + excl; }
        int total = sh[31];
        __syncthreads();
        if (t == 0) carry = c + total;
        __syncthreads();
    }
    if (t == 0) g_rowptr[n] = carry;
}

__global__ void k_fill(const void* __restrict__ ei, int E, int n) {
    int i = blockIdx.x * blockDim.x + threadIdx.x;
    if (i >= E + n) return;
    int is32 = g_is32;
    int v, s;
    if (i < E) {
        s = edge_at(ei, i, is32);
        v = edge_at(ei, (long long)E + i, is32);
    } else {
        v = s = i - E;
    }
    if ((unsigned)v >= (unsigned)n || (unsigned)s >= (unsigned)n) return;
    int p = atomicAdd(&g_wp[v], 1);
    if ((unsigned)p < (unsigned)(E + n)) g_col[p] = s;
}

// ---------------- SGEMM: C[M,N] = A[M,K] @ B[K,N] (+bias, relu optional) -------
// asel < 0 : A = Aext (external input);  else A = selbuf(asel). C = selbuf(csel).
template <bool BIAS, bool RELU>
__global__ void k_sgemm(const float* __restrict__ Aext, const float* __restrict__ B,
                        const float* __restrict__ bias, int asel, int csel,
                        int M, int N, int K) {
    const float* __restrict__ A = (asel < 0) ? Aext : selbuf(asel);
    float* __restrict__ C = selbuf(csel);
    __shared__ float As[16][68];
    __shared__ float Bs[16][68];
    int tid = threadIdx.x;  // 256
    int ty = tid >> 4, tx = tid & 15;
    int bm = blockIdx.y * 64, bn = blockIdx.x * 64;
    int ar = tid >> 2, ac = (tid & 3) << 2;
    int br = tid >> 4, bc = (tid & 15) << 2;
    float acc[4][4];
    #pragma unroll
    for (int i = 0; i < 4; i++)
        #pragma unroll
        for (int j = 0; j < 4; j++) acc[i][j] = 0.f;

    for (int k0 = 0; k0 < K; k0 += 16) {
        int gm = bm + ar;
        float4 av = make_float4(0.f, 0.f, 0.f, 0.f);
        if (gm < M) av = *(const float4*)(A + (size_t)gm * K + k0 + ac);
        As[ac + 0][ar] = av.x; As[ac + 1][ar] = av.y;
        As[ac + 2][ar] = av.z; As[ac + 3][ar] = av.w;

        int gk = k0 + br, gn = bn + bc;
        float4 bv;
        if (((N & 3) == 0) && (gn + 3 < N)) {
            bv = *(const float4*)(B + (size_t)gk * N + gn);
        } else {
            bv.x = (gn + 0 < N) ? B[(size_t)gk * N + gn + 0] : 0.f;
            bv.y = (gn + 1 < N) ? B[(size_t)gk * N + gn + 1] : 0.f;
            bv.z = (gn + 2 < N) ? B[(size_t)gk * N + gn + 2] : 0.f;
            bv.w = (gn + 3 < N) ? B[(size_t)gk * N + gn + 3] : 0.f;
        }
        Bs[br][bc + 0] = bv.x; Bs[br][bc + 1] = bv.y;
        Bs[br][bc + 2] = bv.z; Bs[br][bc + 3] = bv.w;
        __syncthreads();

        #pragma unroll
        for (int kk = 0; kk < 16; kk++) {
            float a[4], b[4];
            #pragma unroll
            for (int i = 0; i < 4; i++) a[i] = As[kk][ty * 4 + i];
            #pragma unroll
            for (int j = 0; j < 4; j++) b[j] = Bs[kk][tx * 4 + j];
            #pragma unroll
            for (int i = 0; i < 4; i++)
                #pragma unroll
                for (int j = 0; j < 4; j++) acc[i][j] += a[i] * b[j];
        }
        __syncthreads();
    }

    #pragma unroll
    for (int i = 0; i < 4; i++) {
        int row = bm + ty * 4 + i;
        if (row >= M) continue;
        #pragma unroll
        for (int j = 0; j < 4; j++) {
            int cn = bn + tx * 4 + j;
            if (cn >= N) continue;
            float v = acc[i][j];
            if (BIAS) v += bias[cn];
            if (RELU) v = fmaxf(v, 0.f);
            C[(size_t)row * N + cn] = v;
        }
    }
}

// ---------------- attention coefficients: a_s/a_d per (node, head) ------------
// reads g_h, writes g_as/g_ad
__global__ void k_attn(const float* __restrict__ att_s, const float* __restrict__ att_d,
                       int n, int H) {
    int idx = blockIdx.x * blockDim.x + threadIdx.x;
    if (idx >= n * H) return;
    int node = idx / H, hh = idx - node * H;
    const float4* hp = (const float4*)(g_h + (size_t)node * H * 64 + hh * 64);
    const float4* sp = (const float4*)(att_s + hh * 64);
    const float4* dp = (const float4*)(att_d + hh * 64);
    float ss = 0.f, dd = 0.f;
    #pragma unroll
    for (int i = 0; i < 16; i++) {
        float4 hv = hp[i], sv = sp[i], dv = dp[i];
        ss += hv.x * sv.x + hv.y * sv.y + hv.z * sv.z + hv.w * sv.w;
        dd += hv.x * dv.x + hv.y * dv.y + hv.z * dv.z + hv.w * dv.w;
    }
    g_as[idx] = ss;
    g_ad[idx] = dd;
}

// ---------------- GAT gather: segment softmax + weighted mean over heads -------
// one warp per dst node; lanes = channels (c, c+32); edges iterated serially.
template <int H, bool BNRELU>
__global__ void k_gather(const float* __restrict__ bias,
                         const float* __restrict__ bng, const float* __restrict__ bnb,
                         const float* __restrict__ bnm, const float* __restrict__ bnv,
                         int osel, int n) {
    float* __restrict__ out = selbuf(osel);
    int w = (blockIdx.x * blockDim.x + threadIdx.x) >> 5;
    int lane = threadIdx.x & 31;
    if (w >= n) return;
    int start = g_rowptr[w], end = g_rowptr[w + 1];

    float adl[H], m[H];
    #pragma unroll
    for (int h = 0; h < H; h++) { adl[h] = g_ad[w * H + h]; m[h] = -1e30f; }

    // pass 1: per-head max over in-edges (edge-parallel across lanes)
    for (int j = start + lane; j < end; j += 32) {
        int s = g_col[j];
        #pragma unroll
        for (int h = 0; h < H; h++) {
            float e = g_as[s * H + h] + adl[h];
            e = (e > 0.f) ? e : 0.2f * e;
            m[h] = fmaxf(m[h], e);
        }
    }
    #pragma unroll
    for (int h = 0; h < H; h++)
        #pragma unroll
        for (int o = 16; o > 0; o >>= 1)
            m[h] = fmaxf(m[h], __shfl_xor_sync(0xffffffffu, m[h], o));

    // pass 2: exp-weighted accumulation (channel-parallel across lanes)
    float acc0[H], acc1[H], den[H];
    #pragma unroll
    for (int h = 0; h < H; h++) { acc0[h] = 0.f; acc1[h] = 0.f; den[h] = 0.f; }
    for (int j = start; j < end; j++) {
        int s = g_col[j];
        const float* hr = g_h + (size_t)s * (H * 64);
        #pragma unroll
        for (int h = 0; h < H; h++) {
            float e = g_as[s * H + h] + adl[h];
            e = (e > 0.f) ? e : 0.2f * e;
            float wgt = __expf(e - m[h]);
            den[h] += wgt;
            acc0[h] += wgt * hr[h * 64 + lane];
            acc1[h] += wgt * hr[h * 64 + 32 + lane];
        }
    }

    float y0 = 0.f, y1 = 0.f;
    #pragma unroll
    for (int h = 0; h < H; h++) {
        float inv = 1.f / (den[h] + 1e-16f);
        y0 += acc0[h] * inv;
        y1 += acc1[h] * inv;
    }
    const float invH = 1.f / (float)H;   // mean over heads (H=1 => identity)
    y0 *= invH; y1 *= invH;
    int c0 = lane, c1 = lane + 32;
    y0 += bias[c0]; y1 += bias[c1];
    if (BNRELU) {
        y0 = (y0 - bnm[c0]) * bng[c0] * rsqrtf(bnv[c0] + 1e-5f) + bnb[c0];
        y1 = (y1 - bnm[c1]) * bng[c1] * rsqrtf(bnv[c1] + 1e-5f) + bnb[c1];
        y0 = fmaxf(y0, 0.f);
        y1 = fmaxf(y1, 0.f);
    }
    out[(size_t)w * 64 + c0] = y0;
    out[(size_t)w * 64 + c1] = y1;
}

// ---------------- row softmax over C=50 classes (warp per node) ----------------
__global__ void k_softmax(float* __restrict__ out, int n, int C) {
    const float* __restrict__ logits = g_h;
    int w = (blockIdx.x * blockDim.x + threadIdx.x) >> 5;
    int lane = threadIdx.x & 31;
    if (w >= n) return;
    float v0 = (lane < C) ? logits[(size_t)w * C + lane] : -1e30f;
    float v1 = (lane + 32 < C) ? logits[(size_t)w * C + lane + 32] : -1e30f;
    float mx = fmaxf(v0, v1);
    #pragma unroll
    for (int o = 16; o > 0; o >>= 1) mx = fmaxf(mx, __shfl_xor_sync(0xffffffffu, mx, o));
    float e0 = (lane < C) ? __expf(v0 - mx) : 0.f;
    float e1 = (lane + 32 < C) ? __expf(v1 - mx) : 0.f;
    float s = e0 + e1;
    #pragma unroll
    for (int o = 16; o > 0; o >>= 1) s += __shfl_xor_sync(0xffffffffu, s, o);
    float inv = 1.f / s;
    if (lane < C) out[(size_t)w * C + lane] = e0 * inv;
    if (lane + 32 < C) out[(size_t)w * C + lane + 32] = e1 * inv;
}

// ---------------- host orchestration ----------------
extern "C" void kernel_launch(void* const* d_in, const int* in_sizes, int n_in,
                              void* d_out, int out_size) {
    const float* x   = (const float*)d_in[0];
    const void*  ei  = d_in[1];
    const float* W1  = (const float*)d_in[2];
    const float* as1 = (const float*)d_in[3];
    const float* ad1 = (const float*)d_in[4];
    const float* b1  = (const float*)d_in[5];
    const float* W2  = (const float*)d_in[6];
    const float* as2 = (const float*)d_in[7];
    const float* ad2 = (const float*)d_in[8];
    const float* b2  = (const float*)d_in[9];
    const float* W3  = (const float*)d_in[10];
    const float* as3 = (const float*)d_in[11];
    const float* ad3 = (const float*)d_in[12];
    const float* b3  = (const float*)d_in[13];
    const float* bn1g = (const float*)d_in[14];
    const float* bn1b = (const float*)d_in[15];
    const float* bn1m = (const float*)d_in[16];
    const float* bn1v = (const float*)d_in[17];
    const float* bn2g = (const float*)d_in[18];
    const float* bn2b = (const float*)d_in[19];
    const float* bn2m = (const float*)d_in[20];
    const float* bn2v = (const float*)d_in[21];
    const float* cW1 = (const float*)d_in[22];
    const float* cb1 = (const float*)d_in[23];
    const float* cW2 = (const float*)d_in[24];
    const float* cb2 = (const float*)d_in[25];

    int n = in_sizes[0] / 256;   // 50000
    int E = in_sizes[1] / 2;     // 400000
    float* out = (float*)d_out;

    // edge dtype detection + CSR by dst (with self loops)
    k_detect<<<1, 32>>>(ei, n);
    k_initdeg<<<(n + 255) / 256, 256>>>(n);
    k_hist<<<(E + 255) / 256, 256>>>(ei, E, n);
    k_scan<<<1, 1024>>>(n);
    k_fill<<<(E + n + 255) / 256, 256>>>(ei, E, n);

    // layer 1: H=8   (h = x @ W1 -> g_h[ n x 512 ])
    {
        dim3 grid(512 / 64, (n + 63) / 64);
        k_sgemm<false, false><<<grid, 256>>>(x, W1, nullptr, -1, 0, n, 512, 256);
    }
    k_attn<<<(n * 8 + 255) / 256, 256>>>(as1, ad1, n, 8);
    k_gather<8, true><<<(n * 32 + 255) / 256, 256>>>(b1, bn1g, bn1b, bn1m, bn1v, 1, n);

    // layer 2: H=4   (h = f1 @ W2 -> g_h[ n x 256 ])
    {
        dim3 grid(256 / 64, (n + 63) / 64);
        k_sgemm<false, false><<<grid, 256>>>(nullptr, W2, nullptr, 1, 0, n, 256, 64);
    }
    k_attn<<<(n * 4 + 255) / 256, 256>>>(as2, ad2, n, 4);
    k_gather<4, true><<<(n * 32 + 255) / 256, 256>>>(b2, bn2g, bn2b, bn2m, bn2v, 2, n);

    // layer 3: H=1, concat   (h = f2 @ W3 -> g_h[ n x 64 ])
    {
        dim3 grid(1, (n + 63) / 64);
        k_sgemm<false, false><<<grid, 256>>>(nullptr, W3, nullptr, 2, 0, n, 64, 64);
    }
    k_attn<<<(n * 1 + 255) / 256, 256>>>(as3, ad3, n, 1);
    k_gather<1, false><<<(n * 32 + 255) / 256, 256>>>(b3, nullptr, nullptr, nullptr, nullptr, 1, n);

    // classifier: z = relu(f1 @ cW1 + cb1) -> f2 ; logits = f2 @ cW2 + cb2 -> g_h ; softmax
    {
        dim3 grid(1, (n + 63) / 64);
        k_sgemm<true, true><<<grid, 256>>>(nullptr, cW1, cb1, 1, 2, n, 64, 64);
    }
    {
        dim3 grid(1, (n + 63) / 64);
        k_sgemm<true, false><<<grid, 256>>>(nullptr, cW2, cb2, 2, 0, n, 50, 64);
    }
    k_softmax<<<(n * 32 + 255) / 256, 256>>>(out, n, 50);
}